// round 11
// baseline (speedup 1.0000x reference)
#include <cuda_runtime.h>
#include <cuda_bf16.h>
#include <cstdint>

#define THREADS      256
#define TILE_FLOATS  2048                    // 8KB per tile
#define TILE_BYTES   (TILE_FLOATS * 4)
#define TILES_PER_CTA 2

__device__ __forceinline__ float ex2_approx(float v) {
    float r; asm("ex2.approx.f32 %0, %1;" : "=f"(r) : "f"(v)); return r;
}
__device__ __forceinline__ float rcp_approx(float v) {
    float r; asm("rcp.approx.f32 %0, %1;" : "=f"(r) : "f"(v)); return r;
}
__device__ __forceinline__ uint32_t smem_u32(const void* p) {
    uint32_t a;
    asm("{ .reg .u64 t; cvta.to.shared.u64 t, %1; cvt.u32.u64 %0, t; }" : "=r"(a) : "l"(p));
    return a;
}

__device__ __forceinline__ void mbar_wait(uint32_t mb) {
    uint32_t done;
    asm volatile(
        "{\n\t.reg .pred p;\n\t"
        "mbarrier.try_wait.parity.acquire.cta.shared::cta.b64 p, [%1], 0;\n\t"
        "selp.b32 %0, 1, 0, p;\n\t}"
        : "=r"(done) : "r"(mb) : "memory");
    if (!done) {
        asm volatile(
            "{\n\t.reg .pred P1;\n\t"
            "WL_%=:\n\t"
            "mbarrier.try_wait.parity.acquire.cta.shared::cta.b64 P1, [%0], 0, 0x989680;\n\t"
            "@P1 bra.uni WD_%=;\n\t"
            "bra.uni WL_%=;\n\t"
            "WD_%=:\n\t}"
            :: "r"(mb) : "memory");
    }
}

// 256-bit store with TRUE L2 evict_first priority (sanctioned sm_103 shape).
// Output lines are write-only and re-dirtied every replay -> evict them first
// so they never displace x; also halves store instruction count.
__device__ __forceinline__ void stg256_ef(float* p, const float* v) {
    asm volatile("st.global.L2::evict_first.v8.b32 [%0], {%1,%2,%3,%4,%5,%6,%7,%8};"
                 :: "l"(p),
                    "r"(__float_as_uint(v[0])), "r"(__float_as_uint(v[1])),
                    "r"(__float_as_uint(v[2])), "r"(__float_as_uint(v[3])),
                    "r"(__float_as_uint(v[4])), "r"(__float_as_uint(v[5])),
                    "r"(__float_as_uint(v[6])), "r"(__float_as_uint(v[7]))
                 : "memory");
}

// Bulk-async loads (evict_last policy on x) + 256-bit evict_first stores.
// 2 front-issued tiles/CTA, 1024 CTAs = single wave. Analytic tanh (EX2+RCP)
// + rint nearest-of-64-uniform-levels, pure register compute.
__global__ void __launch_bounds__(THREADS) quantizer_kernel(
    const float* __restrict__ x,
    float* __restrict__ out_vals,
    float* __restrict__ out_idx,
    int write_idx)
{
    __shared__ alignas(16) float tv[TILES_PER_CTA][TILE_FLOATS];   // x tiles
    __shared__ alignas(8)  unsigned long long mbar[TILES_PER_CTA];

    const int tid = threadIdx.x;
    const size_t gbase = (size_t)blockIdx.x * (TILES_PER_CTA * TILE_FLOATS);

    uint32_t s_tv[TILES_PER_CTA], s_mb[TILES_PER_CTA];
    #pragma unroll
    for (int s = 0; s < TILES_PER_CTA; s++) {
        s_tv[s] = smem_u32(tv[s]);
        s_mb[s] = smem_u32(&mbar[s]);
    }

    if (tid == 0) {
        #pragma unroll
        for (int s = 0; s < TILES_PER_CTA; s++)
            asm volatile("mbarrier.init.shared.b64 [%0], %1;" :: "r"(s_mb[s]), "r"(1) : "memory");
        asm volatile("fence.proxy.async.shared::cta;" ::: "memory");

        // L2 policy: keep x resident (evict_last).
        uint64_t pol;
        asm volatile("createpolicy.fractional.L2::evict_last.b64 %0, 1.0;" : "=l"(pol));

        #pragma unroll
        for (int s = 0; s < TILES_PER_CTA; s++) {
            asm volatile("mbarrier.arrive.expect_tx.shared.b64 _, [%0], %1;"
                         :: "r"(s_mb[s]), "r"((uint32_t)TILE_BYTES) : "memory");
            asm volatile("cp.async.bulk.shared::cta.global.mbarrier::complete_tx::bytes"
                         ".L2::cache_hint [%0], [%1], %2, [%3], %4;"
                         :: "r"(s_tv[s]), "l"(x + gbase + s * TILE_FLOATS),
                            "r"((uint32_t)TILE_BYTES), "r"(s_mb[s]), "l"(pol)
                         : "memory");
        }
    }
    __syncthreads();

    const float TWO_LOG2E = 2.8853900817779268f;   // 2*log2(e)
    const float STEP      = 2.0f / 63.0f;

    #pragma unroll
    for (int s = 0; s < TILES_PER_CTA; s++) {
        mbar_wait(s_mb[s]);

        const size_t tbase = gbase + (size_t)s * TILE_FLOATS;

        // Thread tid owns 8 consecutive floats [tid*8, tid*8+8): two LDS.128,
        // one 32B STG.256 per output plane; warp covers 1KB contiguous.
        float vin[8];
        {
            float4 a = reinterpret_cast<const float4*>(tv[s])[tid * 2 + 0];
            float4 b = reinterpret_cast<const float4*>(tv[s])[tid * 2 + 1];
            vin[0]=a.x; vin[1]=a.y; vin[2]=a.z; vin[3]=a.w;
            vin[4]=b.x; vin[5]=b.y; vin[6]=b.z; vin[7]=b.w;
        }

        float qv[8], qi[8];
        #pragma unroll
        for (int k = 0; k < 8; k++) {
            float xk = vin[k];
            float ax = fabsf(xk);
            // tanh(|x|) = 1 - 2/(exp(2|x|)+1)
            float e    = ex2_approx(ax * TWO_LOG2E);
            float r    = rcp_approx(e + 1.0f);
            float tmag = fmaf(-2.0f, r, 1.0f);
            float t    = copysignf(tmag, xk);
            // nearest of 64 uniform levels in [-1,1]
            float f  = fmaf(t, 31.5f, 31.5f);
            float cf = rintf(f);
            qv[k] = fmaf(cf, STEP, -1.0f);
            qi[k] = cf;
        }

        size_t off = tbase + (size_t)tid * 8;
        stg256_ef(out_vals + off, qv);
        if (write_idx)
            stg256_ef(out_idx + off, qi);
    }
}

extern "C" void kernel_launch(void* const* d_in, const int* in_sizes, int n_in,
                              void* d_out, int out_size) {
    const float* x = (const float*)d_in[0];
    float* out     = (float*)d_out;

    int n = in_sizes[0];            // 4194304 = 2^22
    int write_idx = (out_size >= 2 * n) ? 1 : 0;
    float* out_idx = out + n;

    int elems_per_cta = TILES_PER_CTA * TILE_FLOATS;        // 4096
    int blocks = (n + elems_per_cta - 1) / elems_per_cta;   // 1024

    quantizer_kernel<<<blocks, THREADS>>>(x, out, out_idx, write_idx);
}

// round 12
// speedup vs baseline: 1.0363x; 1.0363x over previous
#include <cuda_runtime.h>
#include <cuda_bf16.h>
#include <cstdint>

#define THREADS      256
#define TILE_FLOATS  1024                    // 4KB per tile
#define TILE_BYTES   (TILE_FLOATS * 4)
#define TILES_PER_CTA 4                      // 16KB x per CTA, bulk MLP=4

__device__ __forceinline__ float ex2_approx(float v) {
    float r; asm("ex2.approx.f32 %0, %1;" : "=f"(r) : "f"(v)); return r;
}
__device__ __forceinline__ float rcp_approx(float v) {
    float r; asm("rcp.approx.f32 %0, %1;" : "=f"(r) : "f"(v)); return r;
}
__device__ __forceinline__ uint32_t smem_u32(const void* p) {
    uint32_t a;
    asm("{ .reg .u64 t; cvta.to.shared.u64 t, %1; cvt.u32.u64 %0, t; }" : "=r"(a) : "l"(p));
    return a;
}

__device__ __forceinline__ void mbar_wait(uint32_t mb) {
    uint32_t done;
    asm volatile(
        "{\n\t.reg .pred p;\n\t"
        "mbarrier.try_wait.parity.acquire.cta.shared::cta.b64 p, [%1], 0;\n\t"
        "selp.b32 %0, 1, 0, p;\n\t}"
        : "=r"(done) : "r"(mb) : "memory");
    if (!done) {
        asm volatile(
            "{\n\t.reg .pred P1;\n\t"
            "WL_%=:\n\t"
            "mbarrier.try_wait.parity.acquire.cta.shared::cta.b64 P1, [%0], 0, 0x989680;\n\t"
            "@P1 bra.uni WD_%=;\n\t"
            "bra.uni WL_%=;\n\t"
            "WD_%=:\n\t}"
            :: "r"(mb) : "memory");
    }
}

// Deep-pipelined streaming quantizer: 4 x 4KB tiles per CTA, all bulk G2S
// loads front-issued (MLP=4). Tile i's compute + STG overlap delivery of
// tiles i+1..3, interleaving read and write traffic chip-wide instead of
// running them as separate phases. 1024 CTAs = single wave.
__global__ void __launch_bounds__(THREADS) quantizer_kernel(
    const float* __restrict__ x,
    float* __restrict__ out_vals,
    float* __restrict__ out_idx,
    int write_idx)
{
    __shared__ alignas(16) float tv[TILES_PER_CTA][TILE_FLOATS];   // x tiles
    __shared__ alignas(8)  unsigned long long mbar[TILES_PER_CTA];

    const int tid = threadIdx.x;
    const size_t gbase = (size_t)blockIdx.x * (TILES_PER_CTA * TILE_FLOATS);

    uint32_t s_tv[TILES_PER_CTA], s_mb[TILES_PER_CTA];
    #pragma unroll
    for (int s = 0; s < TILES_PER_CTA; s++) {
        s_tv[s] = smem_u32(tv[s]);
        s_mb[s] = smem_u32(&mbar[s]);
    }

    if (tid == 0) {
        #pragma unroll
        for (int s = 0; s < TILES_PER_CTA; s++)
            asm volatile("mbarrier.init.shared.b64 [%0], %1;" :: "r"(s_mb[s]), "r"(1) : "memory");
        asm volatile("fence.proxy.async.shared::cta;" ::: "memory");
        // Front-issue ALL tile loads: bulk-level MLP=4.
        #pragma unroll
        for (int s = 0; s < TILES_PER_CTA; s++) {
            asm volatile("mbarrier.arrive.expect_tx.shared.b64 _, [%0], %1;"
                         :: "r"(s_mb[s]), "r"((uint32_t)TILE_BYTES) : "memory");
            asm volatile("cp.async.bulk.shared::cta.global.mbarrier::complete_tx::bytes "
                         "[%0], [%1], %2, [%3];"
                         :: "r"(s_tv[s]), "l"(x + gbase + s * TILE_FLOATS),
                            "r"((uint32_t)TILE_BYTES), "r"(s_mb[s])
                         : "memory");
        }
    }
    __syncthreads();

    const float TWO_LOG2E = 2.8853900817779268f;   // 2*log2(e)
    const float STEP      = 2.0f / 63.0f;

    #pragma unroll
    for (int s = 0; s < TILES_PER_CTA; s++) {
        mbar_wait(s_mb[s]);

        const size_t tbase = gbase + (size_t)s * TILE_FLOATS;

        // Thread tid owns 4 consecutive floats: one LDS.128, one STG.128 per
        // plane. Lanes 16B apart -> conflict-free; warp covers 512B contiguous.
        float4 a = reinterpret_cast<const float4*>(tv[s])[tid];
        float vin[4] = {a.x, a.y, a.z, a.w};
        float qv[4], qi[4];

        #pragma unroll
        for (int k = 0; k < 4; k++) {
            float xk = vin[k];
            float ax = fabsf(xk);
            // tanh(|x|) = 1 - 2/(exp(2|x|)+1)
            float e    = ex2_approx(ax * TWO_LOG2E);
            float r    = rcp_approx(e + 1.0f);
            float tmag = fmaf(-2.0f, r, 1.0f);
            float t    = copysignf(tmag, xk);
            // nearest of 64 uniform levels in [-1,1]
            float f  = fmaf(t, 31.5f, 31.5f);
            float cf = rintf(f);
            qv[k] = fmaf(cf, STEP, -1.0f);
            qi[k] = cf;
        }

        size_t off = tbase + (size_t)tid * 4;
        *reinterpret_cast<float4*>(out_vals + off) =
            make_float4(qv[0], qv[1], qv[2], qv[3]);
        if (write_idx)
            *reinterpret_cast<float4*>(out_idx + off) =
                make_float4(qi[0], qi[1], qi[2], qi[3]);
    }
}

extern "C" void kernel_launch(void* const* d_in, const int* in_sizes, int n_in,
                              void* d_out, int out_size) {
    const float* x = (const float*)d_in[0];
    float* out     = (float*)d_out;

    int n = in_sizes[0];            // 4194304 = 2^22
    int write_idx = (out_size >= 2 * n) ? 1 : 0;
    float* out_idx = out + n;

    int elems_per_cta = TILES_PER_CTA * TILE_FLOATS;        // 4096
    int blocks = (n + elems_per_cta - 1) / elems_per_cta;   // 1024

    quantizer_kernel<<<blocks, THREADS>>>(x, out, out_idx, write_idx);
}